// round 1
// baseline (speedup 1.0000x reference)
#include <cuda_runtime.h>
#include <cuda_bf16.h>
#include <cstdint>

// Problem constants (all powers of two)
//   updates/mask: [B=16, H=128, W=128, C=64]  -> N = 16,777,216 elements
//   output:       [B=16, OH=256, OW=256, C=64] -> 67,108,864 floats (268 MB)
// Index decode:  m in [0, OH*OW*C) ; OW*C = 1<<14 ; C = 1<<6
//   y = m >> 14 ; x = (m >> 6) & 255 ; out = (b<<22) | (y<<14) | (x<<6) | c
// which simplifies further: (y<<14)|(x<<6) == (m >> 6) << 6 == m & ~63.
// So out_idx = (b<<22) | (m & ~63) | c.   (channel replaced by source channel)

static constexpr int N_ELEMS = 16 * 128 * 128 * 64;   // 16,777,216
static constexpr int HWC     = 128 * 128 * 64;        // 1,048,576 = 1<<20
static constexpr int OUT_PER_B_SHIFT = 22;            // OH*OW*C = 1<<22

__global__ void __launch_bounds__(256)
unpool_scatter_kernel(const float4* __restrict__ upd4,
                      const int4*   __restrict__ msk4,
                      float* __restrict__ out)
{
    int i4 = blockIdx.x * blockDim.x + threadIdx.x;   // index in units of 4 elems
    // N_ELEMS/4 = 4,194,304 threads exactly covers the tensor; grid sized to match.
    int i = i4 << 2;                                  // element index of lane 0 of this quad
    int b = i >> 20;                                  // batch (HWC = 1<<20)
    int c = i & 63;                                   // channel of first element (quad stays in-channel-run)

    float4 u = __ldg(&upd4[i4]);
    int4   m = __ldg(&msk4[i4]);

    int base_b = b << OUT_PER_B_SHIFT;

    // out_idx = base_b | (m & ~63) | (c + lane)
    atomicAdd(&out[base_b | (m.x & ~63) | (c + 0)], u.x);
    atomicAdd(&out[base_b | (m.y & ~63) | (c + 1)], u.y);
    atomicAdd(&out[base_b | (m.z & ~63) | (c + 2)], u.z);
    atomicAdd(&out[base_b | (m.w & ~63) | (c + 3)], u.w);
}

extern "C" void kernel_launch(void* const* d_in, const int* in_sizes, int n_in,
                              void* d_out, int out_size)
{
    const float4* upd4 = (const float4*)d_in[0];
    const int4*   msk4 = (const int4*)d_in[1];
    float* out = (float*)d_out;

    // Zero the output (memset node is graph-capturable).
    cudaMemsetAsync(d_out, 0, (size_t)out_size * sizeof(float), 0);

    int n4 = N_ELEMS / 4;                    // 4,194,304
    int threads = 256;
    int blocks = n4 / threads;               // 16,384
    unpool_scatter_kernel<<<blocks, threads>>>(upd4, msk4, out);
}

// round 2
// speedup vs baseline: 1.3938x; 1.3938x over previous
#include <cuda_runtime.h>
#include <cuda_bf16.h>
#include <cstdint>

// MaxUnpooling2D scatter-add.
//   updates/mask: [B=16, H=128, W=128, C=64]  -> N = 16,777,216 elements
//   output:       [B=16, OH=256, OW=256, C=64] -> 67,108,864 floats (268 MB)
//
// out_idx = (b<<22) | (mask & ~63) | c     (channel comes from the source element)
//
// Strategy: per-batch L2-resident zero+scatter fusion.
//   - Output region of ONE batch = 16.7 MB << 126 MB L2.
//   - Kernel k(b) runs scatter(b) and zero(b+1) concurrently in one grid
//     (independent work; kernel boundaries order zero(b) before scatter(b)).
//   - Atomic RMWs then hit dirty-zero lines in L2; output bytes reach DRAM
//     exactly once (natural eviction by later batches).

static constexpr int B_DIM          = 16;
static constexpr int HWC            = 128 * 128 * 64;   // 1<<20 elements per batch (input)
static constexpr int OUT_PER_B      = 1 << 22;          // 256*256*64 floats per batch (output)

static constexpr int THREADS        = 256;
static constexpr int SCATTER_QUADS  = HWC / 4;                    // 262,144 float4 per batch
static constexpr int SCATTER_BLOCKS = SCATTER_QUADS / THREADS;    // 1024
static constexpr int ZERO_VEC4      = OUT_PER_B / 4;              // 1,048,576 float4 per batch
static constexpr int ZERO_BLOCKS    = ZERO_VEC4 / THREADS;        // 4096

// ---------------------------------------------------------------------------
// Scatter one batch: upd4/msk4 pre-offset to batch start; out pre-offset to
// the batch's output region.
__device__ __forceinline__ void scatter_batch(const float4* __restrict__ upd4,
                                              const int4*   __restrict__ msk4,
                                              float* __restrict__ out,
                                              int block)
{
    int i4 = block * THREADS + threadIdx.x;   // quad index within batch
    int c  = (i4 << 2) & 63;                  // channel of first lane of quad

    float4 u = __ldg(&upd4[i4]);
    int4   m = __ldg(&msk4[i4]);

    // atomicAdd with unused return -> REDG (no return latency)
    atomicAdd(&out[(m.x & ~63) | (c + 0)], u.x);
    atomicAdd(&out[(m.y & ~63) | (c + 1)], u.y);
    atomicAdd(&out[(m.z & ~63) | (c + 2)], u.z);
    atomicAdd(&out[(m.w & ~63) | (c + 3)], u.w);
}

__device__ __forceinline__ void zero_batch(float4* __restrict__ out4, int block)
{
    out4[block * THREADS + threadIdx.x] = make_float4(0.f, 0.f, 0.f, 0.f);
}

// ---------------------------------------------------------------------------
// Standalone zero for batch 0 (prologue).
__global__ void __launch_bounds__(THREADS)
zero_kernel(float4* __restrict__ out4)
{
    zero_batch(out4, blockIdx.x);
}

// Fused: scatter batch b (blocks [0, SCATTER_BLOCKS)) + zero batch b+1
// (blocks [SCATTER_BLOCKS, SCATTER_BLOCKS+ZERO_BLOCKS)).
__global__ void __launch_bounds__(THREADS)
scatter_zero_kernel(const float4* __restrict__ upd4,   // batch b updates
                    const int4*   __restrict__ msk4,   // batch b mask
                    float* __restrict__ out_b,         // batch b output region
                    float4* __restrict__ out4_next)    // batch b+1 output region
{
    int blk = blockIdx.x;
    if (blk < SCATTER_BLOCKS) {
        scatter_batch(upd4, msk4, out_b, blk);
    } else {
        zero_batch(out4_next, blk - SCATTER_BLOCKS);
    }
}

// Epilogue: scatter only (last batch).
__global__ void __launch_bounds__(THREADS)
scatter_kernel(const float4* __restrict__ upd4,
               const int4*   __restrict__ msk4,
               float* __restrict__ out_b)
{
    scatter_batch(upd4, msk4, out_b, blockIdx.x);
}

// ---------------------------------------------------------------------------
extern "C" void kernel_launch(void* const* d_in, const int* in_sizes, int n_in,
                              void* d_out, int out_size)
{
    const float4* upd4 = (const float4*)d_in[0];
    const int4*   msk4 = (const int4*)d_in[1];
    float*        out  = (float*)d_out;

    // Prologue: zero batch 0's output region.
    zero_kernel<<<ZERO_BLOCKS, THREADS>>>((float4*)out);

    // Steady state: scatter(b) || zero(b+1)
    for (int b = 0; b < B_DIM - 1; b++) {
        scatter_zero_kernel<<<SCATTER_BLOCKS + ZERO_BLOCKS, THREADS>>>(
            upd4 + (size_t)b * SCATTER_QUADS,
            msk4 + (size_t)b * SCATTER_QUADS,
            out  + (size_t)b * OUT_PER_B,
            (float4*)(out + (size_t)(b + 1) * OUT_PER_B));
    }

    // Epilogue: scatter last batch.
    int b = B_DIM - 1;
    scatter_kernel<<<SCATTER_BLOCKS, THREADS>>>(
        upd4 + (size_t)b * SCATTER_QUADS,
        msk4 + (size_t)b * SCATTER_QUADS,
        out  + (size_t)b * OUT_PER_B);
}